// round 1
// baseline (speedup 1.0000x reference)
#include <cuda_runtime.h>
#include <cuda_bf16.h>
#include <math.h>

#define BATCH 4096
#define NNB   64
#define DM    256
#define NH    8
#define HD    32
#define SCALE 0.17677669529663687f   // 1/sqrt(32)

// ---------------- scratch (__device__ globals: no allocation) ----------------
__device__ float d_Q  [BATCH * DM];        // Q projection             [B,256]
__device__ float d_U  [BATCH * NH * DM];   // u = scale * Qh^T Wk_h    [B,8,256]
__device__ float d_kb [BATCH * NH];        // scale * Qh . bk_h        [B,8]
__device__ float d_ctx[BATCH * NH * DM];   // attn-weighted nb         [B,8,256]
__device__ float d_att[BATCH * DM];        // attn_out (after Wv,bv)   [B,256]
__device__ float d_o  [BATCH * DM];        // attn_out @ Wo^T + bo     [B,256]
__device__ float d_y  [BATCH * DM];        // pre-LN                   [B,256]
__device__ float d_WkT[NH * DM * HD];      // Wk transposed per head   [8][256][32]
__device__ int   d_eflag;                  // 1 => edge types are int64

// ---------------- edge-type dtype detection ----------------
// int64 little-endian values 0..7 have every odd 32-bit word == 0.
// int32 random values 0..7: odd words almost surely contain nonzero.
__global__ void detect_etype_kernel(const unsigned int* e, int nwords) {
    __shared__ unsigned int s;
    if (threadIdx.x == 0) s = 0u;
    __syncthreads();
    unsigned int acc = 0u;
    for (int i = threadIdx.x * 2 + 1; i < nwords; i += 2 * blockDim.x)
        acc |= e[i];
    #pragma unroll
    for (int o = 16; o; o >>= 1) acc |= __shfl_xor_sync(0xffffffffu, acc, o);
    if ((threadIdx.x & 31) == 0) atomicOr(&s, acc);
    __syncthreads();
    if (threadIdx.x == 0) d_eflag = (s == 0u) ? 1 : 0;
}

// ---------------- Wk per-head transpose: WkT[h][c][d] = Wk[h*32+d][c] --------
__global__ void wk_transpose_kernel(const float* __restrict__ Wk) {
    int i = blockIdx.x * 256 + threadIdx.x;      // 65536 total
    int dd = i & 31;
    int c  = (i >> 5) & 255;
    int h  = i >> 13;
    d_WkT[i] = Wk[(h * HD + dd) * DM + c];
}

// ---------------- kbias: kb[b][h] = SCALE * sum_d Q[b,h*32+d]*bk[h*32+d] -----
__global__ void kbias_kernel(const float* __restrict__ bk) {
    int i = blockIdx.x * 256 + threadIdx.x;      // 32768 total
    int h = i & 7, b = i >> 3;
    const float* q  = d_Q + b * DM + h * HD;
    const float* bb = bk + h * HD;
    float s = 0.f;
    #pragma unroll
    for (int dd = 0; dd < HD; dd++) s += q[dd] * bb[dd];
    d_kb[i] = s * SCALE;
}

// ---------------- generic NT GEMM: C = alpha*A.B^T + bias(+beta*C) -----------
// A[M,K] lda, B[N,K] ldb, per-z offsets az/bz/biasz/cz (elements).
// Block computes BM x BN; blockDim.x must be (BM/TM)*(BN/TN).
template<int BM, int BN, int BK, int TM, int TN>
__global__ void gemm_nt_kernel(const float* __restrict__ A, int lda, long az,
                               const float* __restrict__ B, int ldb, long bz,
                               const float* __restrict__ bias, long biasz,
                               float* __restrict__ C, int ldc, long cz,
                               int K, float alpha, int beta) {
    __shared__ float As[BK][BM + 1];
    __shared__ float Bs[BK][BN + 1];
    const int NT = (BM / TM) * (BN / TN);
    const int tx = threadIdx.x % (BN / TN);
    const int ty = threadIdx.x / (BN / TN);
    const int row0 = blockIdx.y * BM;
    const int col0 = blockIdx.x * BN;
    A += (long)blockIdx.z * az;
    B += (long)blockIdx.z * bz;
    C += (long)blockIdx.z * cz;
    if (bias) bias += (long)blockIdx.z * biasz;

    float acc[TM][TN];
    #pragma unroll
    for (int i = 0; i < TM; i++)
        #pragma unroll
        for (int j = 0; j < TN; j++) acc[i][j] = 0.f;

    for (int k0 = 0; k0 < K; k0 += BK) {
        #pragma unroll
        for (int i = threadIdx.x; i < BM * BK; i += NT) {
            int kk = i % BK, m = i / BK;
            As[kk][m] = A[(long)(row0 + m) * lda + k0 + kk];
        }
        #pragma unroll
        for (int i = threadIdx.x; i < BN * BK; i += NT) {
            int kk = i % BK, n = i / BK;
            Bs[kk][n] = B[(long)(col0 + n) * ldb + k0 + kk];
        }
        __syncthreads();
        #pragma unroll
        for (int kk = 0; kk < BK; kk++) {
            float af[TM], bfr[TN];
            #pragma unroll
            for (int i = 0; i < TM; i++) af[i] = As[kk][ty * TM + i];
            #pragma unroll
            for (int j = 0; j < TN; j++) bfr[j] = Bs[kk][tx * TN + j];
            #pragma unroll
            for (int i = 0; i < TM; i++)
                #pragma unroll
                for (int j = 0; j < TN; j++) acc[i][j] += af[i] * bfr[j];
        }
        __syncthreads();
    }
    #pragma unroll
    for (int i = 0; i < TM; i++) {
        int r = row0 + ty * TM + i;
        #pragma unroll
        for (int j = 0; j < TN; j++) {
            int c = col0 + tx * TN + j;
            float v = alpha * acc[i][j];
            if (bias) v += bias[c];
            long idx = (long)r * ldc + c;
            if (beta) v += C[idx];
            C[idx] = v;
        }
    }
}

// ---------------- fused attention kernel (one CTA per batch row) -------------
// smem: nb [64][257], u [8*256], part [4*64*8], logit [512], attn [512],
//       table [64], kb [8], etype [64]
#define NB_STRIDE 257
#define ATTN_SMEM_FLOATS (NNB * NB_STRIDE + NH * DM + 4 * NNB * NH + 512 + 512 + 64 + 8)
#define ATTN_SMEM_BYTES  (ATTN_SMEM_FLOATS * 4 + NNB * 4)

__global__ void attn_kernel(const float* __restrict__ nb,
                            const unsigned int* __restrict__ e32,
                            const float* __restrict__ ebt) {
    extern __shared__ float sm[];
    float* nb_s  = sm;                              // 64*257
    float* u_s   = nb_s + NNB * NB_STRIDE;          // 2048
    float* part  = u_s + NH * DM;                   // 2048  [(q*64+n)*8+h]
    float* logit = part + 4 * NNB * NH;             // 512   [h*64+n]
    float* attn  = logit + 512;                     // 512
    float* tbl   = attn + 512;                      // 64
    float* kb_s  = tbl + 64;                        // 8
    int*   et_s  = (int*)(kb_s + 8);                // 64

    const int b = blockIdx.x;
    const int t = threadIdx.x;

    // loads (fully coalesced, conflict-free stores)
    const float* nbg = nb + (long)b * NNB * DM;
    #pragma unroll 8
    for (int i = 0; i < NNB; i++) nb_s[i * NB_STRIDE + t] = nbg[i * DM + t];
    #pragma unroll
    for (int i = 0; i < NH; i++) u_s[i * DM + t] = d_U[(long)b * NH * DM + i * DM + t];
    if (t < NNB) {
        int v = d_eflag ? (int)e32[(long)b * (2 * NNB) + 2 * t]
                        : (int)e32[(long)b * NNB + t];
        et_s[t] = v;
    }
    if (t < 64) tbl[t] = ebt[t];
    if (t < NH) kb_s[t] = d_kb[b * NH + t];
    __syncthreads();

    // logits partials: thread = (n = t%64, quarter q = t/64 of the 256 c's)
    {
        const int n = t & 63, q = t >> 6;
        const float* nr = nb_s + n * NB_STRIDE + q * 64;
        const float* ur = u_s + q * 64;
        float a[NH];
        #pragma unroll
        for (int h = 0; h < NH; h++) a[h] = 0.f;
        #pragma unroll 8
        for (int c = 0; c < 64; c++) {
            float x = nr[c];                    // conflict-free (stride 257)
            #pragma unroll
            for (int h = 0; h < NH; h++) a[h] += ur[h * DM + c] * x;  // uniform
        }
        float* p = part + (q * 64 + n) * NH;
        #pragma unroll
        for (int h = 0; h < NH; h++) p[h] = a[h];
    }
    __syncthreads();

    // combine partials + kbias + edge bias
    for (int idx = t; idx < NH * NNB; idx += 256) {
        int h = idx >> 6, n = idx & 63;
        float l = kb_s[h] + tbl[et_s[n] * NH + h];
        #pragma unroll
        for (int q = 0; q < 4; q++) l += part[(q * 64 + n) * NH + h];
        logit[h * 64 + n] = l;
    }
    __syncthreads();

    // softmax: warp w handles head h=w over 64 logits
    {
        const int w = t >> 5, l = t & 31;
        float v1 = logit[w * 64 + l];
        float v2 = logit[w * 64 + 32 + l];
        float m = fmaxf(v1, v2);
        #pragma unroll
        for (int o = 16; o; o >>= 1) m = fmaxf(m, __shfl_xor_sync(0xffffffffu, m, o));
        float e1 = __expf(v1 - m), e2 = __expf(v2 - m);
        float s = e1 + e2;
        #pragma unroll
        for (int o = 16; o; o >>= 1) s += __shfl_xor_sync(0xffffffffu, s, o);
        float inv = 1.f / s;
        attn[w * 64 + l]      = e1 * inv;
        attn[w * 64 + 32 + l] = e2 * inv;
    }
    __syncthreads();

    // ctx[h,c] = sum_n attn[h,n]*nb[n,c]; thread = column c
    {
        float a[NH];
        #pragma unroll
        for (int h = 0; h < NH; h++) a[h] = 0.f;
        const float* col = nb_s + t;
        #pragma unroll 8
        for (int n = 0; n < NNB; n++) {
            float x = col[n * NB_STRIDE];       // conflict-free (consecutive c)
            #pragma unroll
            for (int h = 0; h < NH; h++) a[h] += attn[h * 64 + n] * x;  // uniform
        }
        float* cg = d_ctx + (long)b * NH * DM + t;
        #pragma unroll
        for (int h = 0; h < NH; h++) cg[h * DM] = a[h];
    }
}

// ---------------- LayerNorm + ReLU (warp per row) ----------------
__global__ void ln_relu_kernel(const float* __restrict__ g,
                               const float* __restrict__ be,
                               float* __restrict__ out) {
    const int b = blockIdx.x * 8 + (threadIdx.x >> 5);
    const int l = threadIdx.x & 31;
    const float* yr = d_y + (long)b * DM;
    float v[8];
    float s = 0.f;
    #pragma unroll
    for (int i = 0; i < 8; i++) { v[i] = yr[l + i * 32]; s += v[i]; }
    #pragma unroll
    for (int o = 16; o; o >>= 1) s += __shfl_xor_sync(0xffffffffu, s, o);
    float mu = s * (1.f / 256.f);
    float vs = 0.f;
    #pragma unroll
    for (int i = 0; i < 8; i++) { float d = v[i] - mu; vs += d * d; }
    #pragma unroll
    for (int o = 16; o; o >>= 1) vs += __shfl_xor_sync(0xffffffffu, vs, o);
    float r = rsqrtf(vs * (1.f / 256.f) + 1e-5f);
    #pragma unroll
    for (int i = 0; i < 8; i++) {
        int j = l + i * 32;
        float y = (v[i] - mu) * r * g[j] + be[j];
        out[(long)b * DM + j] = fmaxf(y, 0.f);
    }
}

// ---------------- host launcher ----------------
extern "C" void kernel_launch(void* const* d_in, const int* in_sizes, int n_in,
                              void* d_out, int out_size) {
    const float* cde = (const float*)d_in[0];
    const float* nb  = (const float*)d_in[1];
    const unsigned int* et = (const unsigned int*)d_in[2];
    const float* Wq = (const float*)d_in[3];
    const float* bq = (const float*)d_in[4];
    const float* Wk = (const float*)d_in[5];
    const float* bk = (const float*)d_in[6];
    const float* Wv = (const float*)d_in[7];
    const float* bv = (const float*)d_in[8];
    const float* Wo = (const float*)d_in[9];
    const float* bo = (const float*)d_in[10];
    const float* ebt = (const float*)d_in[11];
    const float* Wf = (const float*)d_in[12];
    const float* bf = (const float*)d_in[13];
    const float* lg = (const float*)d_in[14];
    const float* lb = (const float*)d_in[15];
    float* out = (float*)d_out;

    float *pQ, *pU, *pCtx, *pAtt, *pO, *pY, *pWkT;
    cudaGetSymbolAddress((void**)&pQ,   d_Q);
    cudaGetSymbolAddress((void**)&pU,   d_U);
    cudaGetSymbolAddress((void**)&pCtx, d_ctx);
    cudaGetSymbolAddress((void**)&pAtt, d_att);
    cudaGetSymbolAddress((void**)&pO,   d_o);
    cudaGetSymbolAddress((void**)&pY,   d_y);
    cudaGetSymbolAddress((void**)&pWkT, d_WkT);

    cudaFuncSetAttribute(attn_kernel,
                         cudaFuncAttributeMaxDynamicSharedMemorySize,
                         ATTN_SMEM_BYTES);

    // 0) edge dtype detect + Wk transpose
    detect_etype_kernel<<<1, 256>>>(et, BATCH * NNB);
    wk_transpose_kernel<<<NH * DM * HD / 256, 256>>>(Wk);

    // 1) Q = cde @ Wq^T + bq
    gemm_nt_kernel<64, 64, 32, 4, 4><<<dim3(DM / 64, BATCH / 64, 1), 256>>>(
        cde, DM, 0, Wq, DM, 0, bq, 0, pQ, DM, 0, DM, 1.f, 0);

    // 2) U[b,h,:] = SCALE * Qh^T Wk_h   (per-head GEMM, K=32)
    gemm_nt_kernel<64, 64, 32, 4, 4><<<dim3(DM / 64, BATCH / 64, NH), 256>>>(
        pQ, DM, HD, pWkT, HD, (long)DM * HD, nullptr, 0,
        pU, NH * DM, DM, HD, SCALE, 0);

    // 3) kbias
    kbias_kernel<<<BATCH * NH / 256, 256>>>(bk);

    // 4) fused attention: logits -> softmax -> ctx
    attn_kernel<<<BATCH, 256, ATTN_SMEM_BYTES>>>(nb, et, ebt);

    // 5) attn_out[b, h*32+d] = Wv_h[d,:].ctx[b,h,:] + bv  (per-head GEMM)
    gemm_nt_kernel<64, 32, 32, 4, 2><<<dim3(1, BATCH / 64, NH), 256>>>(
        pCtx, NH * DM, DM, Wv, DM, (long)HD * DM, bv, HD,
        pAtt, DM, HD, DM, 1.f, 0);

    // 6) o = attn_out @ Wo^T + bo
    gemm_nt_kernel<64, 64, 32, 4, 4><<<dim3(DM / 64, BATCH / 64, 1), 256>>>(
        pAtt, DM, 0, Wo, DM, 0, bo, 0, pO, DM, 0, DM, 1.f, 0);

    // 7) y = o @ Wf[:, :256]^T + bf ;  y += cde @ Wf[:, 256:]^T
    gemm_nt_kernel<64, 64, 32, 4, 4><<<dim3(DM / 64, BATCH / 64, 1), 256>>>(
        pO, DM, 0, Wf, 2 * DM, 0, bf, 0, pY, DM, 0, DM, 1.f, 0);
    gemm_nt_kernel<64, 64, 32, 4, 4><<<dim3(DM / 64, BATCH / 64, 1), 256>>>(
        cde, DM, 0, Wf + DM, 2 * DM, 0, nullptr, 0, pY, DM, 0, DM, 1.f, 1);

    // 8) LayerNorm + ReLU -> out
    ln_relu_kernel<<<BATCH / 8, 256>>>(lg, lb, out);
}

// round 2
// speedup vs baseline: 1.1357x; 1.1357x over previous
#include <cuda_runtime.h>
#include <cuda_bf16.h>
#include <math.h>

#define BATCH 4096
#define NNB   64
#define DM    256
#define NH    8
#define HD    32
#define SCALE 0.17677669529663687f   // 1/sqrt(32)

// ---------------- scratch (__device__ globals: no allocation) ----------------
__device__ float d_Q  [BATCH * DM];        // Q projection             [B,256]
__device__ float d_U  [BATCH * NH * DM];   // u = scale * Qh^T Wk_h    [B,8,256]
__device__ float d_ctx[BATCH * NH * DM];   // attn-weighted nb         [B,8,256]
__device__ float d_att[BATCH * DM];        // attn_out (after Wv,bv)   [B,256]
__device__ float d_y  [BATCH * DM];        // pre-LN                   [B,256]
__device__ float d_WkT[NH * DM * HD];      // Wk transposed per head   [8][256][32]
__device__ float d_WoT[DM * DM];           // Wo transposed
__device__ float d_Wc [DM * DM];           // Wf1 @ Wo
__device__ float d_b1 [DM];                // bf + Wf1 @ bo
__device__ int   d_eflag;                  // 1 => edge types are int64

// ---------------- edge-type dtype detection ----------------
__global__ void detect_etype_kernel(const unsigned int* e, int nwords) {
    __shared__ unsigned int s;
    if (threadIdx.x == 0) s = 0u;
    __syncthreads();
    unsigned int acc = 0u;
    for (int i = threadIdx.x * 2 + 1; i < nwords; i += 2 * blockDim.x)
        acc |= e[i];
    #pragma unroll
    for (int o = 16; o; o >>= 1) acc |= __shfl_xor_sync(0xffffffffu, acc, o);
    if ((threadIdx.x & 31) == 0) atomicOr(&s, acc);
    __syncthreads();
    if (threadIdx.x == 0) d_eflag = (s == 0u) ? 1 : 0;
}

// ---------------- small transposes ----------------
__global__ void wk_transpose_kernel(const float* __restrict__ Wk) {
    int i = blockIdx.x * 256 + threadIdx.x;      // 65536
    int dd = i & 31;
    int c  = (i >> 5) & 255;
    int h  = i >> 13;
    d_WkT[i] = Wk[(h * HD + dd) * DM + c];
}
__global__ void wo_transpose_kernel(const float* __restrict__ Wo) {
    int i = blockIdx.x * 256 + threadIdx.x;      // 65536
    int j = i >> 8, m = i & 255;
    d_WoT[i] = Wo[m * DM + j];
}

// ---------------- b1 = bf + Wf[:, :256] @ bo  (warp per output) -------------
__global__ void b1_kernel(const float* __restrict__ Wf,
                          const float* __restrict__ bo,
                          const float* __restrict__ bfv) {
    int o = blockIdx.x;
    int l = threadIdx.x;
    float s = 0.f;
    #pragma unroll
    for (int m = l; m < DM; m += 32) s += Wf[o * 2 * DM + m] * bo[m];
    #pragma unroll
    for (int off = 16; off; off >>= 1) s += __shfl_xor_sync(0xffffffffu, s, off);
    if (l == 0) d_b1[o] = bfv[o] + s;
}

// ---------------- double-buffered NT GEMM with optional dual K-source -------
// C[r,c] = alpha * ( sum_{k<K1} A1[r,k]B1[c,k] + sum_{k>=K1} A2[r,k-K1]B2[c,k-K1] ) + bias[c]
// BK must be 16. K1 and Ktot multiples of BK. M mult of BM, N mult of BN.
template<int BM, int BN, int TM, int TN>
__global__ void gemm2_kernel(const float* __restrict__ A1, int lda1, long az1,
                             const float* __restrict__ B1, int ldb1, long bz1,
                             const float* __restrict__ A2, int lda2,
                             const float* __restrict__ B2, int ldb2,
                             const float* __restrict__ bias, long biasz,
                             float* __restrict__ C, int ldc, long cz,
                             int K1, int Ktot, float alpha) {
    constexpr int BK = 16;
    constexpr int NT = (BM / TM) * (BN / TN);
    constexpr int PAD = 4;
    constexpr int A4 = BM * BK / 4;
    constexpr int B4 = BN * BK / 4;
    constexpr int NA = (A4 + NT - 1) / NT;
    constexpr int NB = (B4 + NT - 1) / NT;

    __shared__ float As[2][BK][BM + PAD];
    __shared__ float Bs[2][BK][BN + PAD];

    const int tid = threadIdx.x;
    const int tx = tid % (BN / TN);
    const int ty = tid / (BN / TN);
    const int row0 = blockIdx.y * BM;
    const int col0 = blockIdx.x * BN;
    const int z = blockIdx.z;

    const float* A1g = A1 + (long)z * az1;
    const float* B1g = B1 + (long)z * bz1;
    float* Cg = C + (long)z * cz;
    const float* biasg = bias ? bias + (long)z * biasz : nullptr;

    float4 ra[NA], rb[NB];

    auto fetch = [&](int t) {
        int k0 = t * BK;
        const float *Ap, *Bp; int lda, ldb, k;
        if (k0 < K1) { Ap = A1g; lda = lda1; Bp = B1g; ldb = ldb1; k = k0; }
        else         { Ap = A2;  lda = lda2; Bp = B2;  ldb = ldb2; k = k0 - K1; }
        #pragma unroll
        for (int i = 0; i < NA; i++) {
            int f = tid + i * NT;
            if (f < A4) {
                int r = f >> 2, kq = f & 3;
                ra[i] = *reinterpret_cast<const float4*>(Ap + (long)(row0 + r) * lda + k + kq * 4);
            }
        }
        #pragma unroll
        for (int i = 0; i < NB; i++) {
            int f = tid + i * NT;
            if (f < B4) {
                int n = f >> 2, kq = f & 3;
                rb[i] = *reinterpret_cast<const float4*>(Bp + (long)(col0 + n) * ldb + k + kq * 4);
            }
        }
    };
    auto stage = [&](int buf) {
        #pragma unroll
        for (int i = 0; i < NA; i++) {
            int f = tid + i * NT;
            if (f < A4) {
                int r = f >> 2, kq = f & 3;
                As[buf][kq * 4 + 0][r] = ra[i].x;
                As[buf][kq * 4 + 1][r] = ra[i].y;
                As[buf][kq * 4 + 2][r] = ra[i].z;
                As[buf][kq * 4 + 3][r] = ra[i].w;
            }
        }
        #pragma unroll
        for (int i = 0; i < NB; i++) {
            int f = tid + i * NT;
            if (f < B4) {
                int n = f >> 2, kq = f & 3;
                Bs[buf][kq * 4 + 0][n] = rb[i].x;
                Bs[buf][kq * 4 + 1][n] = rb[i].y;
                Bs[buf][kq * 4 + 2][n] = rb[i].z;
                Bs[buf][kq * 4 + 3][n] = rb[i].w;
            }
        }
    };

    float acc[TM][TN];
    #pragma unroll
    for (int i = 0; i < TM; i++)
        #pragma unroll
        for (int j = 0; j < TN; j++) acc[i][j] = 0.f;

    fetch(0); stage(0); __syncthreads();
    const int ntiles = Ktot / BK;
    for (int t = 0; t < ntiles; t++) {
        int cur = t & 1;
        if (t + 1 < ntiles) fetch(t + 1);
        #pragma unroll
        for (int kk = 0; kk < BK; kk++) {
            float a[TM], b[TN];
            #pragma unroll
            for (int i = 0; i < TM; i++) a[i] = As[cur][kk][ty * TM + i];
            #pragma unroll
            for (int j = 0; j < TN; j++) b[j] = Bs[cur][kk][tx * TN + j];
            #pragma unroll
            for (int i = 0; i < TM; i++)
                #pragma unroll
                for (int j = 0; j < TN; j++) acc[i][j] += a[i] * b[j];
        }
        if (t + 1 < ntiles) stage(cur ^ 1);
        __syncthreads();
    }

    #pragma unroll
    for (int i = 0; i < TM; i++) {
        int r = row0 + ty * TM + i;
        #pragma unroll
        for (int j = 0; j < TN; j++) {
            int c = col0 + tx * TN + j;
            float v = alpha * acc[i][j];
            if (biasg) v += biasg[c];
            Cg[(long)r * ldc + c] = v;
        }
    }
}

// ---------------- fused attention kernel (one CTA per batch row) -------------
#define NB_STRIDE 257
#define ATTN_SMEM_FLOATS (NNB * NB_STRIDE + NH * DM + 4 * NNB * NH + 512 + 512 + 64 + 8)
#define ATTN_SMEM_BYTES  (ATTN_SMEM_FLOATS * 4 + NNB * 4)

__global__ void attn_kernel(const float* __restrict__ nb,
                            const unsigned int* __restrict__ e32,
                            const float* __restrict__ ebt,
                            const float* __restrict__ bk) {
    extern __shared__ float sm[];
    float* nb_s  = sm;                              // 64*257
    float* u_s   = nb_s + NNB * NB_STRIDE;          // 2048
    float* part  = u_s + NH * DM;                   // 2048  [(q*64+n)*8+h]
    float* logit = part + 4 * NNB * NH;             // 512   [h*64+n]
    float* attn  = logit + 512;                     // 512
    float* tbl   = attn + 512;                      // 64
    float* kb_s  = tbl + 64;                        // 8
    int*   et_s  = (int*)(kb_s + 8);                // 64

    const int b = blockIdx.x;
    const int t = threadIdx.x;

    // loads (coalesced)
    const float* nbg = nb + (long)b * NNB * DM;
    #pragma unroll 8
    for (int i = 0; i < NNB; i++) nb_s[i * NB_STRIDE + t] = nbg[i * DM + t];
    #pragma unroll
    for (int i = 0; i < NH; i++) u_s[i * DM + t] = d_U[(long)b * NH * DM + i * DM + t];
    if (t < NNB) {
        int v = d_eflag ? (int)e32[(long)b * (2 * NNB) + 2 * t]
                        : (int)e32[(long)b * NNB + t];
        et_s[t] = v;
    }
    if (t < 64) tbl[t] = ebt[t];

    // kbias inline: warp w -> head w
    {
        const int w = t >> 5, l = t & 31;
        float s = d_Q[(long)b * DM + w * HD + l] * bk[w * HD + l];
        #pragma unroll
        for (int o = 16; o; o >>= 1) s += __shfl_xor_sync(0xffffffffu, s, o);
        if (l == 0) kb_s[w] = SCALE * s;
    }
    __syncthreads();

    // logits partials: thread = (n = t%64, quarter q = t/64)
    {
        const int n = t & 63, q = t >> 6;
        const float* nr = nb_s + n * NB_STRIDE + q * 64;
        const float* ur = u_s + q * 64;
        float a[NH];
        #pragma unroll
        for (int h = 0; h < NH; h++) a[h] = 0.f;
        #pragma unroll 8
        for (int c = 0; c < 64; c++) {
            float x = nr[c];
            #pragma unroll
            for (int h = 0; h < NH; h++) a[h] += ur[h * DM + c] * x;
        }
        float* p = part + (q * 64 + n) * NH;
        #pragma unroll
        for (int h = 0; h < NH; h++) p[h] = a[h];
    }
    __syncthreads();

    // combine partials + kbias + edge bias
    for (int idx = t; idx < NH * NNB; idx += 256) {
        int h = idx >> 6, n = idx & 63;
        float l = kb_s[h] + tbl[et_s[n] * NH + h];
        #pragma unroll
        for (int q = 0; q < 4; q++) l += part[(q * 64 + n) * NH + h];
        logit[h * 64 + n] = l;
    }
    __syncthreads();

    // softmax: warp w = head w
    {
        const int w = t >> 5, l = t & 31;
        float v1 = logit[w * 64 + l];
        float v2 = logit[w * 64 + 32 + l];
        float m = fmaxf(v1, v2);
        #pragma unroll
        for (int o = 16; o; o >>= 1) m = fmaxf(m, __shfl_xor_sync(0xffffffffu, m, o));
        float e1 = __expf(v1 - m), e2 = __expf(v2 - m);
        float s = e1 + e2;
        #pragma unroll
        for (int o = 16; o; o >>= 1) s += __shfl_xor_sync(0xffffffffu, s, o);
        float inv = 1.f / s;
        attn[w * 64 + l]      = e1 * inv;
        attn[w * 64 + 32 + l] = e2 * inv;
    }
    __syncthreads();

    // ctx[h,c] = sum_n attn[h,n]*nb[n,c]; thread = column c
    {
        float a[NH];
        #pragma unroll
        for (int h = 0; h < NH; h++) a[h] = 0.f;
        const float* col = nb_s + t;
        #pragma unroll 8
        for (int n = 0; n < NNB; n++) {
            float x = col[n * NB_STRIDE];
            #pragma unroll
            for (int h = 0; h < NH; h++) a[h] += attn[h * 64 + n] * x;
        }
        float* cg = d_ctx + (long)b * NH * DM + t;
        #pragma unroll
        for (int h = 0; h < NH; h++) cg[h * DM] = a[h];
    }
}

// ---------------- LayerNorm + ReLU (warp per row) ----------------
__global__ void ln_relu_kernel(const float* __restrict__ g,
                               const float* __restrict__ be,
                               float* __restrict__ out) {
    const int b = blockIdx.x * 8 + (threadIdx.x >> 5);
    const int l = threadIdx.x & 31;
    const float* yr = d_y + (long)b * DM;
    float v[8];
    float s = 0.f;
    #pragma unroll
    for (int i = 0; i < 8; i++) { v[i] = yr[l + i * 32]; s += v[i]; }
    #pragma unroll
    for (int o = 16; o; o >>= 1) s += __shfl_xor_sync(0xffffffffu, s, o);
    float mu = s * (1.f / 256.f);
    float vs = 0.f;
    #pragma unroll
    for (int i = 0; i < 8; i++) { float d = v[i] - mu; vs += d * d; }
    #pragma unroll
    for (int o = 16; o; o >>= 1) vs += __shfl_xor_sync(0xffffffffu, vs, o);
    float r = rsqrtf(vs * (1.f / 256.f) + 1e-5f);
    #pragma unroll
    for (int i = 0; i < 8; i++) {
        int j = l + i * 32;
        float y = (v[i] - mu) * r * g[j] + be[j];
        out[(long)b * DM + j] = fmaxf(y, 0.f);
    }
}

// ---------------- host launcher ----------------
extern "C" void kernel_launch(void* const* d_in, const int* in_sizes, int n_in,
                              void* d_out, int out_size) {
    const float* cde = (const float*)d_in[0];
    const float* nb  = (const float*)d_in[1];
    const unsigned int* et = (const unsigned int*)d_in[2];
    const float* Wq = (const float*)d_in[3];
    const float* bq = (const float*)d_in[4];
    const float* Wk = (const float*)d_in[5];
    const float* bk = (const float*)d_in[6];
    const float* Wv = (const float*)d_in[7];
    const float* bv = (const float*)d_in[8];
    const float* Wo = (const float*)d_in[9];
    const float* bo = (const float*)d_in[10];
    const float* ebt = (const float*)d_in[11];
    const float* Wf = (const float*)d_in[12];
    const float* bfv = (const float*)d_in[13];
    const float* lg = (const float*)d_in[14];
    const float* lb = (const float*)d_in[15];
    float* out = (float*)d_out;

    float *pQ, *pU, *pCtx, *pAtt, *pY, *pWkT, *pWoT, *pWc, *pB1;
    cudaGetSymbolAddress((void**)&pQ,   d_Q);
    cudaGetSymbolAddress((void**)&pU,   d_U);
    cudaGetSymbolAddress((void**)&pCtx, d_ctx);
    cudaGetSymbolAddress((void**)&pAtt, d_att);
    cudaGetSymbolAddress((void**)&pY,   d_y);
    cudaGetSymbolAddress((void**)&pWkT, d_WkT);
    cudaGetSymbolAddress((void**)&pWoT, d_WoT);
    cudaGetSymbolAddress((void**)&pWc,  d_Wc);
    cudaGetSymbolAddress((void**)&pB1,  d_b1);

    cudaFuncSetAttribute(attn_kernel,
                         cudaFuncAttributeMaxDynamicSharedMemorySize,
                         ATTN_SMEM_BYTES);

    // 0) prep: edge dtype, transposes, weight folds
    detect_etype_kernel<<<1, 256>>>(et, BATCH * NNB);
    wk_transpose_kernel<<<NH * DM * HD / 256, 256>>>(Wk);
    wo_transpose_kernel<<<DM * DM / 256, 256>>>(Wo);
    b1_kernel<<<DM, 32>>>(Wf, bo, bfv);
    // Wc = Wf[:, :256] @ Wo   (via WoT, NT form)
    gemm2_kernel<128, 64, 8, 4><<<dim3(DM / 64, DM / 128, 1), 256>>>(
        Wf, 2 * DM, 0, pWoT, DM, 0, nullptr, 0, nullptr, 0,
        nullptr, 0, pWc, DM, 0, DM, DM, 1.f);

    // 1) Q = cde @ Wq^T + bq
    gemm2_kernel<128, 64, 8, 4><<<dim3(DM / 64, BATCH / 128, 1), 256>>>(
        cde, DM, 0, Wq, DM, 0, nullptr, 0, nullptr, 0,
        bq, 0, pQ, DM, 0, DM, DM, 1.f);

    // 2) U[b,h,:] = SCALE * Qh^T Wk_h   (per-head, K=32)
    gemm2_kernel<128, 64, 8, 4><<<dim3(DM / 64, BATCH / 128, NH), 256>>>(
        pQ, DM, HD, pWkT, HD, (long)DM * HD, nullptr, 0, nullptr, 0,
        nullptr, 0, pU, NH * DM, DM, HD, HD, SCALE);

    // 3) fused attention (kbias inline): logits -> softmax -> ctx
    attn_kernel<<<BATCH, 256, ATTN_SMEM_BYTES>>>(nb, et, ebt, bk);

    // 4) att[b, h*32+d] = Wv_h[d,:].ctx[b,h,:] + bv
    gemm2_kernel<128, 32, 8, 2><<<dim3(1, BATCH / 128, NH), 256>>>(
        pCtx, NH * DM, DM, Wv, DM, (long)HD * DM, nullptr, 0, nullptr, 0,
        bv, HD, pAtt, DM, HD, DM, DM, 1.f);

    // 5) y = att @ Wc^T + cde @ Wf[:,256:]^T + b1   (dual-source K=512)
    gemm2_kernel<128, 64, 8, 4><<<dim3(DM / 64, BATCH / 128, 1), 256>>>(
        pAtt, DM, 0, pWc, DM, 0, cde, DM, Wf + DM, 2 * DM,
        pB1, 0, pY, DM, 0, DM, 2 * DM, 1.f);

    // 6) LayerNorm + ReLU -> out
    ln_relu_kernel<<<BATCH / 8, 256>>>(lg, lb, out);
}

// round 3
// speedup vs baseline: 2.3206x; 2.0433x over previous
#include <cuda_runtime.h>
#include <cuda_bf16.h>
#include <math.h>

#define BATCH 4096
#define NNB   64
#define DM    256
#define NH    8
#define HD    32
#define SCALE 0.17677669529663687f   // 1/sqrt(32)
#define NBS   260                    // nb smem row stride (floats, float4-aligned)

// ---------------- scratch (__device__ globals: no allocation) ----------------
__device__ float d_Q  [BATCH * DM];        // Q projection             [B,256]
__device__ float d_U  [BATCH * NH * DM];   // u = scale * Qh^T Wk_h    [B,8,256]
__device__ float d_ctx[BATCH * NH * DM];   // attn-weighted nb         [B,8,256]
__device__ float d_att[BATCH * DM];        // attn_out (after Wv,bv)   [B,256]
__device__ float d_y  [BATCH * DM];        // pre-LN                   [B,256]
__device__ float d_WkT[NH * DM * HD];      // Wk transposed per head   [8][256][32]
__device__ float d_WoT[DM * DM];           // Wo transposed
__device__ float d_Wc [DM * DM];           // Wf1 @ Wo
__device__ float d_b1 [DM];                // bf + Wf1 @ bo
__device__ unsigned int d_or;              // OR of odd words; 0 => int64 edges

// ---------------- prep: transposes + b1 + flag init (one kernel) -------------
__global__ void prep_kernel(const float* __restrict__ Wk,
                            const float* __restrict__ Wo,
                            const float* __restrict__ Wf,
                            const float* __restrict__ bo,
                            const float* __restrict__ bfv) {
    const int blk = blockIdx.x, t = threadIdx.x;
    const int i = blk * 256 + t;                 // 0..65535
    { int dd = i & 31, c = (i >> 5) & 255, h = i >> 13;
      d_WkT[i] = Wk[(h * HD + dd) * DM + c]; }
    { int j = i >> 8, m = i & 255;
      d_WoT[i] = Wo[m * DM + j]; }
    if (blk == 0 && t == 0) d_or = 0u;
    if (blk < 32) {                              // b1: warp per output
        int o = blk * 8 + (t >> 5), l = t & 31;
        float s = 0.f;
        #pragma unroll
        for (int m = l; m < DM; m += 32) s += Wf[o * 2 * DM + m] * bo[m];
        #pragma unroll
        for (int off = 16; off; off >>= 1) s += __shfl_xor_sync(0xffffffffu, s, off);
        if (l == 0) d_b1[o] = bfv[o] + s;
    }
}

// ---------------- edge dtype detect (64 blocks, OR of odd 32-bit words) ------
__global__ void detect_kernel(const unsigned int* __restrict__ e, int nwords) {
    unsigned int acc = 0u;
    const int stride = gridDim.x * blockDim.x * 2;
    for (int i = (blockIdx.x * blockDim.x + threadIdx.x) * 2 + 1; i < nwords; i += stride)
        acc |= e[i];
    #pragma unroll
    for (int o = 16; o; o >>= 1) acc |= __shfl_xor_sync(0xffffffffu, acc, o);
    __shared__ unsigned int s;
    if (threadIdx.x == 0) s = 0u;
    __syncthreads();
    if ((threadIdx.x & 31) == 0 && acc) atomicOr(&s, acc);
    __syncthreads();
    if (threadIdx.x == 0 && s) atomicOr(&d_or, s);
}

// ---------------- double-buffered NT GEMM with optional dual K-source -------
template<int BM, int BN, int TM, int TN>
__global__ void gemm2_kernel(const float* __restrict__ A1, int lda1, long az1,
                             const float* __restrict__ B1, int ldb1, long bz1,
                             const float* __restrict__ A2, int lda2,
                             const float* __restrict__ B2, int ldb2,
                             const float* __restrict__ bias, long biasz,
                             float* __restrict__ C, int ldc, long cz,
                             int K1, int Ktot, float alpha) {
    constexpr int BK = 16;
    constexpr int NT = (BM / TM) * (BN / TN);
    constexpr int PAD = 4;
    constexpr int A4 = BM * BK / 4;
    constexpr int B4 = BN * BK / 4;
    constexpr int NA = (A4 + NT - 1) / NT;
    constexpr int NB = (B4 + NT - 1) / NT;

    __shared__ float As[2][BK][BM + PAD];
    __shared__ float Bs[2][BK][BN + PAD];

    const int tid = threadIdx.x;
    const int tx = tid % (BN / TN);
    const int ty = tid / (BN / TN);
    const int row0 = blockIdx.y * BM;
    const int col0 = blockIdx.x * BN;
    const int z = blockIdx.z;

    const float* A1g = A1 + (long)z * az1;
    const float* B1g = B1 + (long)z * bz1;
    float* Cg = C + (long)z * cz;
    const float* biasg = bias ? bias + (long)z * biasz : nullptr;

    float4 ra[NA], rb[NB];

    auto fetch = [&](int t) {
        int k0 = t * BK;
        const float *Ap, *Bp; int lda, ldb, k;
        if (k0 < K1) { Ap = A1g; lda = lda1; Bp = B1g; ldb = ldb1; k = k0; }
        else         { Ap = A2;  lda = lda2; Bp = B2;  ldb = ldb2; k = k0 - K1; }
        #pragma unroll
        for (int i = 0; i < NA; i++) {
            int f = tid + i * NT;
            if (f < A4) {
                int r = f >> 2, kq = f & 3;
                ra[i] = *reinterpret_cast<const float4*>(Ap + (long)(row0 + r) * lda + k + kq * 4);
            }
        }
        #pragma unroll
        for (int i = 0; i < NB; i++) {
            int f = tid + i * NT;
            if (f < B4) {
                int n = f >> 2, kq = f & 3;
                rb[i] = *reinterpret_cast<const float4*>(Bp + (long)(col0 + n) * ldb + k + kq * 4);
            }
        }
    };
    auto stage = [&](int buf) {
        #pragma unroll
        for (int i = 0; i < NA; i++) {
            int f = tid + i * NT;
            if (f < A4) {
                int r = f >> 2, kq = f & 3;
                As[buf][kq * 4 + 0][r] = ra[i].x;
                As[buf][kq * 4 + 1][r] = ra[i].y;
                As[buf][kq * 4 + 2][r] = ra[i].z;
                As[buf][kq * 4 + 3][r] = ra[i].w;
            }
        }
        #pragma unroll
        for (int i = 0; i < NB; i++) {
            int f = tid + i * NT;
            if (f < B4) {
                int n = f >> 2, kq = f & 3;
                Bs[buf][kq * 4 + 0][n] = rb[i].x;
                Bs[buf][kq * 4 + 1][n] = rb[i].y;
                Bs[buf][kq * 4 + 2][n] = rb[i].z;
                Bs[buf][kq * 4 + 3][n] = rb[i].w;
            }
        }
    };

    float acc[TM][TN];
    #pragma unroll
    for (int i = 0; i < TM; i++)
        #pragma unroll
        for (int j = 0; j < TN; j++) acc[i][j] = 0.f;

    fetch(0); stage(0); __syncthreads();
    const int ntiles = Ktot / BK;
    for (int t = 0; t < ntiles; t++) {
        int cur = t & 1;
        if (t + 1 < ntiles) fetch(t + 1);
        #pragma unroll
        for (int kk = 0; kk < BK; kk++) {
            float a[TM], b[TN];
            #pragma unroll
            for (int i = 0; i < TM; i++) a[i] = As[cur][kk][ty * TM + i];
            #pragma unroll
            for (int j = 0; j < TN; j++) b[j] = Bs[cur][kk][tx * TN + j];
            #pragma unroll
            for (int i = 0; i < TM; i++)
                #pragma unroll
                for (int j = 0; j < TN; j++) acc[i][j] += a[i] * b[j];
        }
        if (t + 1 < ntiles) stage(cur ^ 1);
        __syncthreads();
    }

    #pragma unroll
    for (int i = 0; i < TM; i++) {
        int r = row0 + ty * TM + i;
        #pragma unroll
        for (int j = 0; j < TN; j++) {
            int c = col0 + tx * TN + j;
            float v = alpha * acc[i][j];
            if (biasg) v += biasg[c];
            Cg[(long)r * ldc + c] = v;
        }
    }
}

// ---------------- fused attention v2 (float4, one CTA per batch row) ---------
// smem floats: nb 64*260, u 2048, part 2048 [h][q][n], logit 512, attn 512,
//              tbl 64, kb 8; + 64 ints
#define ATTN_SMEM_FLOATS (NNB * NBS + 2048 + 2048 + 512 + 512 + 64 + 8)
#define ATTN_SMEM_BYTES  (ATTN_SMEM_FLOATS * 4 + NNB * 4)

__global__ void attn_kernel(const float* __restrict__ nb,
                            const unsigned int* __restrict__ e32,
                            const float* __restrict__ ebt,
                            const float* __restrict__ bk) {
    extern __shared__ float sm[];
    float* nb_s  = sm;                       // 64*260
    float* u_s   = nb_s + NNB * NBS;         // 2048
    float* part  = u_s + 2048;               // 2048  [h*256 + q*64 + n]
    float* logit = part + 2048;              // 512   [h*64+n]
    float* attn_s= logit + 512;              // 512
    float* tbl   = attn_s + 512;             // 64
    float* kb_s  = tbl + 64;                 // 8
    int*   et_s  = (int*)(kb_s + 8);         // 64

    const int b = blockIdx.x;
    const int t = threadIdx.x;

    // ---- loads (float4, coalesced, conflict-free stores) ----
    const float4* nbg = (const float4*)(nb + (long)b * NNB * DM);
    #pragma unroll
    for (int i = 0; i < 16; i++) {
        int f = t + i * 256;
        int row = f >> 6, c4 = f & 63;
        *reinterpret_cast<float4*>(nb_s + row * NBS + c4 * 4) = nbg[f];
    }
    const float4* ug = (const float4*)(d_U + (long)b * 2048);
    *reinterpret_cast<float4*>(u_s + t * 4)        = ug[t];
    *reinterpret_cast<float4*>(u_s + 1024 + t * 4) = ug[256 + t];
    if (t < NNB) {
        int ef = (d_or == 0u);
        int v = ef ? (int)e32[(long)b * (2 * NNB) + 2 * t]
                   : (int)e32[(long)b * NNB + t];
        et_s[t] = v;
        tbl[t] = ebt[t];
    }
    // kbias inline: warp w -> head w
    {
        const int w = t >> 5, l = t & 31;
        float s = d_Q[(long)b * DM + w * HD + l] * bk[w * HD + l];
        #pragma unroll
        for (int o = 16; o; o >>= 1) s += __shfl_xor_sync(0xffffffffu, s, o);
        if (l == 0) kb_s[w] = SCALE * s;
    }
    __syncthreads();

    // ---- logits partials: thread = (n = t&63, quarter q = t>>6), float4 ----
    {
        const int n = t & 63, q = t >> 6;
        const float* xr = nb_s + n * NBS + q * 64;
        const float* ur = u_s + q * 64;
        float acc[NH];
        #pragma unroll
        for (int h = 0; h < NH; h++) acc[h] = 0.f;
        #pragma unroll 4
        for (int c = 0; c < 64; c += 4) {
            float4 x = *reinterpret_cast<const float4*>(xr + c);
            #pragma unroll
            for (int h = 0; h < NH; h++) {
                float4 u = *reinterpret_cast<const float4*>(ur + h * DM + c);
                acc[h] += u.x * x.x + u.y * x.y + u.z * x.z + u.w * x.w;
            }
        }
        #pragma unroll
        for (int h = 0; h < NH; h++) part[h * 256 + q * 64 + n] = acc[h];
    }
    __syncthreads();

    // ---- combine partials + kbias + edge bias ----
    #pragma unroll
    for (int idx = t; idx < NH * NNB; idx += 256) {
        int h = idx >> 6, n = idx & 63;
        float l = kb_s[h] + tbl[et_s[n] * NH + h];
        #pragma unroll
        for (int q = 0; q < 4; q++) l += part[h * 256 + q * 64 + n];
        logit[h * 64 + n] = l;
    }
    __syncthreads();

    // ---- softmax: warp w = head w over 64 logits ----
    {
        const int w = t >> 5, l = t & 31;
        float v1 = logit[w * 64 + l];
        float v2 = logit[w * 64 + 32 + l];
        float m = fmaxf(v1, v2);
        #pragma unroll
        for (int o = 16; o; o >>= 1) m = fmaxf(m, __shfl_xor_sync(0xffffffffu, m, o));
        float e1 = __expf(v1 - m), e2 = __expf(v2 - m);
        float s = e1 + e2;
        #pragma unroll
        for (int o = 16; o; o >>= 1) s += __shfl_xor_sync(0xffffffffu, s, o);
        float inv = 1.f / s;
        attn_s[w * 64 + l]      = e1 * inv;
        attn_s[w * 64 + 32 + l] = e2 * inv;
    }
    __syncthreads();

    // ---- ctx: thread = (c4 = t&63, head-pair hp = t>>6 -> {hp, hp+4}) ----
    {
        const int c4 = t & 63, hp = t >> 6;
        const float* colp = nb_s + c4 * 4;
        const float* a0p = attn_s + hp * 64;
        const float* a1p = attn_s + (hp + 4) * 64;
        float4 a0 = {0.f, 0.f, 0.f, 0.f};
        float4 a1 = {0.f, 0.f, 0.f, 0.f};
        #pragma unroll 8
        for (int n = 0; n < NNB; n++) {
            float4 x = *reinterpret_cast<const float4*>(colp + n * NBS);
            float w0 = a0p[n], w1 = a1p[n];
            a0.x += w0 * x.x; a0.y += w0 * x.y; a0.z += w0 * x.z; a0.w += w0 * x.w;
            a1.x += w1 * x.x; a1.y += w1 * x.y; a1.z += w1 * x.z; a1.w += w1 * x.w;
        }
        float4* cg = (float4*)(d_ctx + (long)b * 2048);
        cg[hp * 64 + c4]       = a0;
        cg[(hp + 4) * 64 + c4] = a1;
    }
}

// ---------------- LayerNorm + ReLU (warp per row) ----------------
__global__ void ln_relu_kernel(const float* __restrict__ g,
                               const float* __restrict__ be,
                               float* __restrict__ out) {
    const int b = blockIdx.x * 8 + (threadIdx.x >> 5);
    const int l = threadIdx.x & 31;
    const float* yr = d_y + (long)b * DM;
    float v[8];
    float s = 0.f;
    #pragma unroll
    for (int i = 0; i < 8; i++) { v[i] = yr[l + i * 32]; s += v[i]; }
    #pragma unroll
    for (int o = 16; o; o >>= 1) s += __shfl_xor_sync(0xffffffffu, s, o);
    float mu = s * (1.f / 256.f);
    float vs = 0.f;
    #pragma unroll
    for (int i = 0; i < 8; i++) { float d = v[i] - mu; vs += d * d; }
    #pragma unroll
    for (int o = 16; o; o >>= 1) vs += __shfl_xor_sync(0xffffffffu, vs, o);
    float r = rsqrtf(vs * (1.f / 256.f) + 1e-5f);
    #pragma unroll
    for (int i = 0; i < 8; i++) {
        int j = l + i * 32;
        float y = (v[i] - mu) * r * g[j] + be[j];
        out[(long)b * DM + j] = fmaxf(y, 0.f);
    }
}

// ---------------- host launcher ----------------
extern "C" void kernel_launch(void* const* d_in, const int* in_sizes, int n_in,
                              void* d_out, int out_size) {
    const float* cde = (const float*)d_in[0];
    const float* nb  = (const float*)d_in[1];
    const unsigned int* et = (const unsigned int*)d_in[2];
    const float* Wq = (const float*)d_in[3];
    const float* bq = (const float*)d_in[4];
    const float* Wk = (const float*)d_in[5];
    const float* bk = (const float*)d_in[6];
    const float* Wv = (const float*)d_in[7];
    const float* bv = (const float*)d_in[8];
    const float* Wo = (const float*)d_in[9];
    const float* bo = (const float*)d_in[10];
    const float* ebt = (const float*)d_in[11];
    const float* Wf = (const float*)d_in[12];
    const float* bfv = (const float*)d_in[13];
    const float* lg = (const float*)d_in[14];
    const float* lb = (const float*)d_in[15];
    float* out = (float*)d_out;

    float *pQ, *pU, *pCtx, *pAtt, *pY, *pWkT, *pWoT, *pWc, *pB1;
    cudaGetSymbolAddress((void**)&pQ,   d_Q);
    cudaGetSymbolAddress((void**)&pU,   d_U);
    cudaGetSymbolAddress((void**)&pCtx, d_ctx);
    cudaGetSymbolAddress((void**)&pAtt, d_att);
    cudaGetSymbolAddress((void**)&pY,   d_y);
    cudaGetSymbolAddress((void**)&pWkT, d_WkT);
    cudaGetSymbolAddress((void**)&pWoT, d_WoT);
    cudaGetSymbolAddress((void**)&pWc,  d_Wc);
    cudaGetSymbolAddress((void**)&pB1,  d_b1);

    cudaFuncSetAttribute(attn_kernel,
                         cudaFuncAttributeMaxDynamicSharedMemorySize,
                         ATTN_SMEM_BYTES);

    // 1) prep (transposes + b1 + flag init)
    prep_kernel<<<256, 256>>>(Wk, Wo, Wf, bo, bfv);
    // 2) edge dtype detect
    detect_kernel<<<64, 256>>>(et, BATCH * NNB);
    // 3) Wc = Wf[:, :256] @ Wo
    gemm2_kernel<128, 64, 8, 4><<<dim3(DM / 64, DM / 128, 1), 256>>>(
        Wf, 2 * DM, 0, pWoT, DM, 0, nullptr, 0, nullptr, 0,
        nullptr, 0, pWc, DM, 0, DM, DM, 1.f);
    // 4) Q = cde @ Wq^T + bq
    gemm2_kernel<128, 64, 8, 4><<<dim3(DM / 64, BATCH / 128, 1), 256>>>(
        cde, DM, 0, Wq, DM, 0, nullptr, 0, nullptr, 0,
        bq, 0, pQ, DM, 0, DM, DM, 1.f);
    // 5) U[b,h,:] = SCALE * Qh^T Wk_h
    gemm2_kernel<128, 64, 8, 4><<<dim3(DM / 64, BATCH / 128, NH), 256>>>(
        pQ, DM, HD, pWkT, HD, (long)DM * HD, nullptr, 0, nullptr, 0,
        nullptr, 0, pU, NH * DM, DM, HD, HD, SCALE);
    // 6) fused attention  (6th launch -> ncu capture target)
    attn_kernel<<<BATCH, 256, ATTN_SMEM_BYTES>>>(nb, et, ebt, bk);
    // 7) att[b, h*32+d] = Wv_h[d,:].ctx[b,h,:] + bv
    gemm2_kernel<128, 32, 8, 2><<<dim3(1, BATCH / 128, NH), 256>>>(
        pCtx, NH * DM, DM, Wv, DM, (long)HD * DM, nullptr, 0, nullptr, 0,
        bv, HD, pAtt, DM, HD, DM, DM, 1.f);
    // 8) y = att @ Wc^T + cde @ Wf[:,256:]^T + b1
    gemm2_kernel<128, 64, 8, 4><<<dim3(DM / 64, BATCH / 128, 1), 256>>>(
        pAtt, DM, 0, pWc, DM, 0, cde, DM, Wf + DM, 2 * DM,
        pB1, 0, pY, DM, 0, DM, 2 * DM, 1.f);
    // 9) LayerNorm + ReLU -> out
    ln_relu_kernel<<<BATCH / 8, 256>>>(lg, lb, out);
}

// round 4
// speedup vs baseline: 2.5198x; 1.0859x over previous
#include <cuda_runtime.h>
#include <cuda_bf16.h>
#include <math.h>

#define BATCH 4096
#define NNB   64
#define DM    256
#define NH    8
#define HD    32
#define SCALE 0.17677669529663687f   // 1/sqrt(32)
#define NBS   260                    // nb smem row stride (floats, float4-aligned)

// ---------------- scratch (__device__ globals: no allocation) ----------------
__device__ float d_Q  [BATCH * DM];
__device__ float d_U  [BATCH * NH * DM];
__device__ float d_ctx[BATCH * NH * DM];
__device__ float d_att[BATCH * DM];
__device__ float d_y  [BATCH * DM];
__device__ float d_WkT[NH * DM * HD];
__device__ float d_WoT[DM * DM];
__device__ float d_Wc [DM * DM];
__device__ float d_b1 [DM];
__device__ unsigned int d_or;              // OR of odd words; 0 => int64 edges

// ---------------- prep: transposes + b1 + flag init ----------------
__global__ void prep_kernel(const float* __restrict__ Wk,
                            const float* __restrict__ Wo,
                            const float* __restrict__ Wf,
                            const float* __restrict__ bo,
                            const float* __restrict__ bfv) {
    const int blk = blockIdx.x, t = threadIdx.x;
    const int i = blk * 256 + t;
    { int dd = i & 31, c = (i >> 5) & 255, h = i >> 13;
      d_WkT[i] = Wk[(h * HD + dd) * DM + c]; }
    { int j = i >> 8, m = i & 255;
      d_WoT[i] = Wo[m * DM + j]; }
    if (blk == 0 && t == 0) d_or = 0u;
    if (blk < 32) {
        int o = blk * 8 + (t >> 5), l = t & 31;
        float s = 0.f;
        #pragma unroll
        for (int m = l; m < DM; m += 32) s += Wf[o * 2 * DM + m] * bo[m];
        #pragma unroll
        for (int off = 16; off; off >>= 1) s += __shfl_xor_sync(0xffffffffu, s, off);
        if (l == 0) d_b1[o] = bfv[o] + s;
    }
}

// ---------------- edge dtype detect ----------------
__global__ void detect_kernel(const unsigned int* __restrict__ e, int nwords) {
    unsigned int acc = 0u;
    const int stride = gridDim.x * blockDim.x * 2;
    for (int i = (blockIdx.x * blockDim.x + threadIdx.x) * 2 + 1; i < nwords; i += stride)
        acc |= e[i];
    #pragma unroll
    for (int o = 16; o; o >>= 1) acc |= __shfl_xor_sync(0xffffffffu, acc, o);
    __shared__ unsigned int s;
    if (threadIdx.x == 0) s = 0u;
    __syncthreads();
    if ((threadIdx.x & 31) == 0 && acc) atomicOr(&s, acc);
    __syncthreads();
    if (threadIdx.x == 0 && s) atomicOr(&d_or, s);
}

// ---------------- double-buffered NT GEMM with optional dual K-source -------
template<int BM, int BN, int TM, int TN>
__global__ void gemm2_kernel(const float* __restrict__ A1, int lda1, long az1,
                             const float* __restrict__ B1, int ldb1, long bz1,
                             const float* __restrict__ A2, int lda2,
                             const float* __restrict__ B2, int ldb2,
                             const float* __restrict__ bias, long biasz,
                             float* __restrict__ C, int ldc, long cz,
                             int K1, int Ktot, float alpha) {
    constexpr int BK = 16;
    constexpr int NT = (BM / TM) * (BN / TN);
    constexpr int PAD = 4;
    constexpr int A4 = BM * BK / 4;
    constexpr int B4 = BN * BK / 4;
    constexpr int NA = (A4 + NT - 1) / NT;
    constexpr int NB = (B4 + NT - 1) / NT;

    __shared__ float As[2][BK][BM + PAD];
    __shared__ float Bs[2][BK][BN + PAD];

    const int tid = threadIdx.x;
    const int tx = tid % (BN / TN);
    const int ty = tid / (BN / TN);
    const int row0 = blockIdx.y * BM;
    const int col0 = blockIdx.x * BN;
    const int z = blockIdx.z;

    const float* A1g = A1 + (long)z * az1;
    const float* B1g = B1 + (long)z * bz1;
    float* Cg = C + (long)z * cz;
    const float* biasg = bias ? bias + (long)z * biasz : nullptr;

    float4 ra[NA], rb[NB];

    auto fetch = [&](int t) {
        int k0 = t * BK;
        const float *Ap, *Bp; int lda, ldb, k;
        if (k0 < K1) { Ap = A1g; lda = lda1; Bp = B1g; ldb = ldb1; k = k0; }
        else         { Ap = A2;  lda = lda2; Bp = B2;  ldb = ldb2; k = k0 - K1; }
        #pragma unroll
        for (int i = 0; i < NA; i++) {
            int f = tid + i * NT;
            if (f < A4) {
                int r = f >> 2, kq = f & 3;
                ra[i] = *reinterpret_cast<const float4*>(Ap + (long)(row0 + r) * lda + k + kq * 4);
            }
        }
        #pragma unroll
        for (int i = 0; i < NB; i++) {
            int f = tid + i * NT;
            if (f < B4) {
                int n = f >> 2, kq = f & 3;
                rb[i] = *reinterpret_cast<const float4*>(Bp + (long)(col0 + n) * ldb + k + kq * 4);
            }
        }
    };
    auto stage = [&](int buf) {
        #pragma unroll
        for (int i = 0; i < NA; i++) {
            int f = tid + i * NT;
            if (f < A4) {
                int r = f >> 2, kq = f & 3;
                As[buf][kq * 4 + 0][r] = ra[i].x;
                As[buf][kq * 4 + 1][r] = ra[i].y;
                As[buf][kq * 4 + 2][r] = ra[i].z;
                As[buf][kq * 4 + 3][r] = ra[i].w;
            }
        }
        #pragma unroll
        for (int i = 0; i < NB; i++) {
            int f = tid + i * NT;
            if (f < B4) {
                int n = f >> 2, kq = f & 3;
                Bs[buf][kq * 4 + 0][n] = rb[i].x;
                Bs[buf][kq * 4 + 1][n] = rb[i].y;
                Bs[buf][kq * 4 + 2][n] = rb[i].z;
                Bs[buf][kq * 4 + 3][n] = rb[i].w;
            }
        }
    };

    float acc[TM][TN];
    #pragma unroll
    for (int i = 0; i < TM; i++)
        #pragma unroll
        for (int j = 0; j < TN; j++) acc[i][j] = 0.f;

    fetch(0); stage(0); __syncthreads();
    const int ntiles = Ktot / BK;
    for (int t = 0; t < ntiles; t++) {
        int cur = t & 1;
        if (t + 1 < ntiles) fetch(t + 1);
        #pragma unroll
        for (int kk = 0; kk < BK; kk++) {
            float a[TM], b[TN];
            #pragma unroll
            for (int i = 0; i < TM; i++) a[i] = As[cur][kk][ty * TM + i];
            #pragma unroll
            for (int j = 0; j < TN; j++) b[j] = Bs[cur][kk][tx * TN + j];
            #pragma unroll
            for (int i = 0; i < TM; i++)
                #pragma unroll
                for (int j = 0; j < TN; j++) acc[i][j] += a[i] * b[j];
        }
        if (t + 1 < ntiles) stage(cur ^ 1);
        __syncthreads();
    }

    #pragma unroll
    for (int i = 0; i < TM; i++) {
        int r = row0 + ty * TM + i;
        #pragma unroll
        for (int j = 0; j < TN; j++) {
            int c = col0 + tx * TN + j;
            float v = alpha * acc[i][j];
            if (biasg) v += biasg[c];
            Cg[(long)r * ldc + c] = v;
        }
    }
}

// ---------------- fused attention (float4, one CTA per batch row) ------------
#define ATTN_SMEM_FLOATS (NNB * NBS + 2048 + 2048 + 512 + 512 + 64 + 8)
#define ATTN_SMEM_BYTES  (ATTN_SMEM_FLOATS * 4 + NNB * 4)

__global__ void attn_kernel(const float* __restrict__ nb,
                            const unsigned int* __restrict__ e32,
                            const float* __restrict__ ebt,
                            const float* __restrict__ bk) {
    extern __shared__ float sm[];
    float* nb_s  = sm;                       // 64*260
    float* u_s   = nb_s + NNB * NBS;         // 2048
    float* part  = u_s + 2048;               // 2048  [h*256 + q*64 + n]
    float* logit = part + 2048;              // 512
    float* attn_s= logit + 512;              // 512
    float* tbl   = attn_s + 512;             // 64
    float* kb_s  = tbl + 64;                 // 8
    int*   et_s  = (int*)(kb_s + 8);         // 64

    const int b = blockIdx.x;
    const int t = threadIdx.x;

    const float4* nbg = (const float4*)(nb + (long)b * NNB * DM);
    #pragma unroll
    for (int i = 0; i < 16; i++) {
        int f = t + i * 256;
        int row = f >> 6, c4 = f & 63;
        *reinterpret_cast<float4*>(nb_s + row * NBS + c4 * 4) = nbg[f];
    }
    const float4* ug = (const float4*)(d_U + (long)b * 2048);
    *reinterpret_cast<float4*>(u_s + t * 4)        = ug[t];
    *reinterpret_cast<float4*>(u_s + 1024 + t * 4) = ug[256 + t];
    if (t < NNB) {
        int ef = (d_or == 0u);
        int v = ef ? (int)e32[(long)b * (2 * NNB) + 2 * t]
                   : (int)e32[(long)b * NNB + t];
        et_s[t] = v;
        tbl[t] = ebt[t];
    }
    {
        const int w = t >> 5, l = t & 31;
        float s = d_Q[(long)b * DM + w * HD + l] * bk[w * HD + l];
        #pragma unroll
        for (int o = 16; o; o >>= 1) s += __shfl_xor_sync(0xffffffffu, s, o);
        if (l == 0) kb_s[w] = SCALE * s;
    }
    __syncthreads();

    {
        const int n = t & 63, q = t >> 6;
        const float* xr = nb_s + n * NBS + q * 64;
        const float* ur = u_s + q * 64;
        float acc[NH];
        #pragma unroll
        for (int h = 0; h < NH; h++) acc[h] = 0.f;
        #pragma unroll 4
        for (int c = 0; c < 64; c += 4) {
            float4 x = *reinterpret_cast<const float4*>(xr + c);
            #pragma unroll
            for (int h = 0; h < NH; h++) {
                float4 u = *reinterpret_cast<const float4*>(ur + h * DM + c);
                acc[h] += u.x * x.x + u.y * x.y + u.z * x.z + u.w * x.w;
            }
        }
        #pragma unroll
        for (int h = 0; h < NH; h++) part[h * 256 + q * 64 + n] = acc[h];
    }
    __syncthreads();

    #pragma unroll
    for (int idx = t; idx < NH * NNB; idx += 256) {
        int h = idx >> 6, n = idx & 63;
        float l = kb_s[h] + tbl[et_s[n] * NH + h];
        #pragma unroll
        for (int q = 0; q < 4; q++) l += part[h * 256 + q * 64 + n];
        logit[h * 64 + n] = l;
    }
    __syncthreads();

    {
        const int w = t >> 5, l = t & 31;
        float v1 = logit[w * 64 + l];
        float v2 = logit[w * 64 + 32 + l];
        float m = fmaxf(v1, v2);
        #pragma unroll
        for (int o = 16; o; o >>= 1) m = fmaxf(m, __shfl_xor_sync(0xffffffffu, m, o));
        float e1 = __expf(v1 - m), e2 = __expf(v2 - m);
        float s = e1 + e2;
        #pragma unroll
        for (int o = 16; o; o >>= 1) s += __shfl_xor_sync(0xffffffffu, s, o);
        float inv = 1.f / s;
        attn_s[w * 64 + l]      = e1 * inv;
        attn_s[w * 64 + 32 + l] = e2 * inv;
    }
    __syncthreads();

    {
        const int c4 = t & 63, hp = t >> 6;
        const float* colp = nb_s + c4 * 4;
        const float* a0p = attn_s + hp * 64;
        const float* a1p = attn_s + (hp + 4) * 64;
        float4 a0 = {0.f, 0.f, 0.f, 0.f};
        float4 a1 = {0.f, 0.f, 0.f, 0.f};
        #pragma unroll 8
        for (int n = 0; n < NNB; n++) {
            float4 x = *reinterpret_cast<const float4*>(colp + n * NBS);
            float w0 = a0p[n], w1 = a1p[n];
            a0.x += w0 * x.x; a0.y += w0 * x.y; a0.z += w0 * x.z; a0.w += w0 * x.w;
            a1.x += w1 * x.x; a1.y += w1 * x.y; a1.z += w1 * x.z; a1.w += w1 * x.w;
        }
        float4* cg = (float4*)(d_ctx + (long)b * 2048);
        cg[hp * 64 + c4]       = a0;
        cg[(hp + 4) * 64 + c4] = a1;
    }
}

// ---------------- LayerNorm + ReLU (warp per row, float4) ----------------
__global__ void ln_relu_kernel(const float* __restrict__ g,
                               const float* __restrict__ be,
                               float* __restrict__ out) {
    const int b = blockIdx.x * 8 + (threadIdx.x >> 5);
    const int l = threadIdx.x & 31;
    const float4* yr = (const float4*)(d_y + (long)b * DM) + l * 2;
    float4 v0 = yr[0], v1 = yr[1];
    float s = v0.x + v0.y + v0.z + v0.w + v1.x + v1.y + v1.z + v1.w;
    #pragma unroll
    for (int o = 16; o; o >>= 1) s += __shfl_xor_sync(0xffffffffu, s, o);
    float mu = s * (1.f / 256.f);
    float vs = 0.f;
    {
        float d;
        d = v0.x - mu; vs += d * d;  d = v0.y - mu; vs += d * d;
        d = v0.z - mu; vs += d * d;  d = v0.w - mu; vs += d * d;
        d = v1.x - mu; vs += d * d;  d = v1.y - mu; vs += d * d;
        d = v1.z - mu; vs += d * d;  d = v1.w - mu; vs += d * d;
    }
    #pragma unroll
    for (int o = 16; o; o >>= 1) vs += __shfl_xor_sync(0xffffffffu, vs, o);
    float r = rsqrtf(vs * (1.f / 256.f) + 1e-5f);
    const float4* gp = (const float4*)g + l * 2;
    const float4* bp = (const float4*)be + l * 2;
    float4* op = (float4*)(out + (long)b * DM) + l * 2;
    float4 g0 = gp[0], g1 = gp[1], b0 = bp[0], b1 = bp[1];
    float4 o0, o1;
    o0.x = fmaxf((v0.x - mu) * r * g0.x + b0.x, 0.f);
    o0.y = fmaxf((v0.y - mu) * r * g0.y + b0.y, 0.f);
    o0.z = fmaxf((v0.z - mu) * r * g0.z + b0.z, 0.f);
    o0.w = fmaxf((v0.w - mu) * r * g0.w + b0.w, 0.f);
    o1.x = fmaxf((v1.x - mu) * r * g1.x + b1.x, 0.f);
    o1.y = fmaxf((v1.y - mu) * r * g1.y + b1.y, 0.f);
    o1.z = fmaxf((v1.z - mu) * r * g1.z + b1.z, 0.f);
    o1.w = fmaxf((v1.w - mu) * r * g1.w + b1.w, 0.f);
    op[0] = o0; op[1] = o1;
}

// ---------------- host launcher ----------------
extern "C" void kernel_launch(void* const* d_in, const int* in_sizes, int n_in,
                              void* d_out, int out_size) {
    const float* cde = (const float*)d_in[0];
    const float* nb  = (const float*)d_in[1];
    const unsigned int* et = (const unsigned int*)d_in[2];
    const float* Wq = (const float*)d_in[3];
    const float* bq = (const float*)d_in[4];
    const float* Wk = (const float*)d_in[5];
    const float* bk = (const float*)d_in[6];
    const float* Wv = (const float*)d_in[7];
    const float* bv = (const float*)d_in[8];
    const float* Wo = (const float*)d_in[9];
    const float* bo = (const float*)d_in[10];
    const float* ebt = (const float*)d_in[11];
    const float* Wf = (const float*)d_in[12];
    const float* bfv = (const float*)d_in[13];
    const float* lg = (const float*)d_in[14];
    const float* lb = (const float*)d_in[15];
    float* out = (float*)d_out;

    float *pQ, *pU, *pCtx, *pAtt, *pY, *pWkT, *pWoT, *pWc, *pB1;
    cudaGetSymbolAddress((void**)&pQ,   d_Q);
    cudaGetSymbolAddress((void**)&pU,   d_U);
    cudaGetSymbolAddress((void**)&pCtx, d_ctx);
    cudaGetSymbolAddress((void**)&pAtt, d_att);
    cudaGetSymbolAddress((void**)&pY,   d_y);
    cudaGetSymbolAddress((void**)&pWkT, d_WkT);
    cudaGetSymbolAddress((void**)&pWoT, d_WoT);
    cudaGetSymbolAddress((void**)&pWc,  d_Wc);
    cudaGetSymbolAddress((void**)&pB1,  d_b1);

    cudaFuncSetAttribute(attn_kernel,
                         cudaFuncAttributeMaxDynamicSharedMemorySize,
                         ATTN_SMEM_BYTES);

    // 1) prep (transposes + b1 + flag init)
    prep_kernel<<<256, 256>>>(Wk, Wo, Wf, bo, bfv);
    // 2) edge dtype detect
    detect_kernel<<<64, 256>>>(et, BATCH * NNB);
    // 3) Q = cde @ Wq^T + bq           (64x64 tiles, 128 thr, grid 256)
    gemm2_kernel<64, 64, 8, 4><<<dim3(DM / 64, BATCH / 64, 1), 128>>>(
        cde, DM, 0, Wq, DM, 0, nullptr, 0, nullptr, 0,
        bq, 0, pQ, DM, 0, DM, DM, 1.f);
    // 4) U[b,h,:] = SCALE * Qh^T Wk_h  (grid 2048)
    gemm2_kernel<64, 64, 8, 4><<<dim3(DM / 64, BATCH / 64, NH), 128>>>(
        pQ, DM, HD, pWkT, HD, (long)DM * HD, nullptr, 0, nullptr, 0,
        nullptr, 0, pU, NH * DM, DM, HD, HD, SCALE);
    // 5) Wc = Wf[:, :256] @ Wo
    gemm2_kernel<64, 64, 8, 4><<<dim3(DM / 64, DM / 64, 1), 128>>>(
        Wf, 2 * DM, 0, pWoT, DM, 0, nullptr, 0, nullptr, 0,
        nullptr, 0, pWc, DM, 0, DM, DM, 1.f);
    // 6) fused attention  (6th launch -> ncu capture target)
    attn_kernel<<<BATCH, 256, ATTN_SMEM_BYTES>>>(nb, et, ebt, bk);
    // 7) att[b, h*32+d] = Wv_h[d,:].ctx[b,h,:] + bv   (128x32 tiles, grid 256)
    gemm2_kernel<128, 32, 8, 2><<<dim3(1, BATCH / 128, NH), 256>>>(
        pCtx, NH * DM, DM, Wv, DM, (long)HD * DM, nullptr, 0, nullptr, 0,
        bv, HD, pAtt, DM, HD, DM, DM, 1.f);
    // 8) y = att @ Wc^T + cde @ Wf[:,256:]^T + b1   (grid 256)
    gemm2_kernel<64, 64, 8, 4><<<dim3(DM / 64, BATCH / 64, 1), 128>>>(
        pAtt, DM, 0, pWc, DM, 0, cde, DM, Wf + DM, 2 * DM,
        pB1, 0, pY, DM, 0, DM, 2 * DM, 1.f);
    // 9) LayerNorm + ReLU -> out
    ln_relu_kernel<<<BATCH / 8, 256>>>(lg, lb, out);
}